// round 3
// baseline (speedup 1.0000x reference)
#include <cuda_runtime.h>
#include <cstdint>

// Problem constants (fixed per reference)
#define NNODES 8192
#define FDIM   1024
#define ODIM   1024
#define KDIM   2048   // 2*FDIM
#define NNB    10

// Scratch for aggregated (mean of sampled neighbors) features: 32 MB
__device__ float g_agg[NNODES * FDIM];

// ---------------------------------------------------------------------------
// Stage 1: agg[row] = mean_j X[sampled_idx[row][j]]
// One block per row, 256 threads, each thread owns one float4 (1024/4 = 256).
// ---------------------------------------------------------------------------
__global__ void __launch_bounds__(256) gather_mean_kernel(
    const float* __restrict__ X, const int* __restrict__ idx)
{
    const int row = blockIdx.x;
    const int t   = threadIdx.x;              // 0..255
    const float4* Xv = reinterpret_cast<const float4*>(X);

    float4 acc = make_float4(0.f, 0.f, 0.f, 0.f);
#pragma unroll
    for (int j = 0; j < NNB; ++j) {
        const int nb = __ldg(idx + row * NNB + j);
        const float4 v = __ldg(Xv + (size_t)nb * (FDIM / 4) + t);
        acc.x += v.x; acc.y += v.y; acc.z += v.z; acc.w += v.w;
    }
    const float s = 1.0f / (float)NNB;
    acc.x *= s; acc.y *= s; acc.z *= s; acc.w *= s;
    reinterpret_cast<float4*>(g_agg)[(size_t)row * (FDIM / 4) + t] = acc;
}

// ---------------------------------------------------------------------------
// Stage 2: out = [X | agg] @ W + b      (M=8192, N=1024, K=2048)
// Tiled fp32 SIMT GEMM using packed fma.rn.f32x2 (FFMA2) for 2x fp32 rate.
// BM=BN=128, BK=16, 256 threads, 8x8 per-thread microtile (acc packed over n).
// ---------------------------------------------------------------------------
#define BM 128
#define BN 128
#define BK 16
#define TM 8
#define TN 8

typedef unsigned long long u64;

__device__ __forceinline__ u64 pack_dup(float a) {
    u64 r;
    asm("mov.b64 %0, {%1, %1};" : "=l"(r) : "r"(__float_as_uint(a)));
    return r;
}
__device__ __forceinline__ void fma_f32x2(u64& d, u64 a, u64 b, u64 c) {
    asm("fma.rn.f32x2 %0, %1, %2, %3;" : "=l"(d) : "l"(a), "l"(b), "l"(c));
}
__device__ __forceinline__ float2 unpack_f32x2(u64 v) {
    float2 f;
    unsigned lo, hi;
    asm("mov.b64 {%0, %1}, %2;" : "=r"(lo), "=r"(hi) : "l"(v));
    f.x = __uint_as_float(lo);
    f.y = __uint_as_float(hi);
    return f;
}

__global__ void __launch_bounds__(256, 2) gemm_concat_kernel(
    const float* __restrict__ X,       // [NNODES, FDIM]
    const float* __restrict__ W,       // [KDIM, ODIM]
    const float* __restrict__ bias,    // [ODIM]
    float* __restrict__ out)           // [NNODES, ODIM]
{
    __shared__ float As[BK][BM + 4];   // transposed A tile, padded stride 132
    __shared__ float Bs[BK][BN];

    const int t  = threadIdx.x;        // 0..255
    const int bm = blockIdx.y;         // 0..63
    const int bn = blockIdx.x;         // 0..7

    const int tx = t & 15;             // n-direction (16 * 8 = 128)
    const int ty = t >> 4;             // m-direction (16 * 8 = 128)

    // A-tile load mapping: 128 rows x 16 k = 512 float4; 2 per thread.
    const int rowA = t >> 2;           // 0..63 (and +64)
    const int kq   = t & 3;            // which float4 along k
    // B-tile load mapping: 16 rows x 32 float4 = 512; 2 per thread.
    const int rB = t >> 5;             // 0..7 (and +8)
    const int cB = t & 31;             // float4 index along n

    u64 acc[TM][TN / 2];
#pragma unroll
    for (int i = 0; i < TM; ++i)
#pragma unroll
        for (int j = 0; j < TN / 2; ++j) acc[i][j] = 0ULL;

    const size_t mbase = (size_t)bm * BM;

    for (int kt = 0; kt < KDIM / BK; ++kt) {
        // Virtual concat: k-tiles [0,64) come from X, [64,128) from g_agg.
        const float* Asrc = (kt < FDIM / BK)
            ? X     + mbase * FDIM + (size_t)kt * BK
            : g_agg + mbase * FDIM + (size_t)(kt - FDIM / BK) * BK;

        const float4 a0 = *reinterpret_cast<const float4*>(
            Asrc + (size_t)rowA * FDIM + kq * 4);
        const float4 a1 = *reinterpret_cast<const float4*>(
            Asrc + (size_t)(rowA + 64) * FDIM + kq * 4);

        const float* Bsrc = W + (size_t)kt * BK * ODIM + (size_t)bn * BN;
        const float4 b0 = *reinterpret_cast<const float4*>(
            Bsrc + (size_t)rB * ODIM + cB * 4);
        const float4 b1 = *reinterpret_cast<const float4*>(
            Bsrc + (size_t)(rB + 8) * ODIM + cB * 4);

        __syncthreads();  // previous iter's smem reads complete

        // Store A transposed: As[k][m]
        As[kq * 4 + 0][rowA] = a0.x;
        As[kq * 4 + 1][rowA] = a0.y;
        As[kq * 4 + 2][rowA] = a0.z;
        As[kq * 4 + 3][rowA] = a0.w;
        As[kq * 4 + 0][rowA + 64] = a1.x;
        As[kq * 4 + 1][rowA + 64] = a1.y;
        As[kq * 4 + 2][rowA + 64] = a1.z;
        As[kq * 4 + 3][rowA + 64] = a1.w;
        *reinterpret_cast<float4*>(&Bs[rB][cB * 4])     = b0;
        *reinterpret_cast<float4*>(&Bs[rB + 8][cB * 4]) = b1;

        __syncthreads();

#pragma unroll
        for (int k = 0; k < BK; ++k) {
            // a fragment: 8 m-values, each duplicated into both f32x2 lanes
            const float4 af0 = *reinterpret_cast<const float4*>(&As[k][ty * TM]);
            const float4 af1 = *reinterpret_cast<const float4*>(&As[k][ty * TM + 4]);
            u64 a2[TM];
            a2[0] = pack_dup(af0.x); a2[1] = pack_dup(af0.y);
            a2[2] = pack_dup(af0.z); a2[3] = pack_dup(af0.w);
            a2[4] = pack_dup(af1.x); a2[5] = pack_dup(af1.y);
            a2[6] = pack_dup(af1.z); a2[7] = pack_dup(af1.w);

            // b fragment: 8 n-values as 4 natural f32x2 pairs
            const ulonglong2 bb0 =
                *reinterpret_cast<const ulonglong2*>(&Bs[k][tx * TN]);
            const ulonglong2 bb1 =
                *reinterpret_cast<const ulonglong2*>(&Bs[k][tx * TN + 4]);
            const u64 b2[4] = { bb0.x, bb0.y, bb1.x, bb1.y };

#pragma unroll
            for (int i = 0; i < TM; ++i) {
#pragma unroll
                for (int j = 0; j < TN / 2; ++j) {
                    fma_f32x2(acc[i][j], a2[i], b2[j], acc[i][j]);
                }
            }
        }
    }

    // Epilogue: unpack, add bias, store
    const int m0 = bm * BM + ty * TM;
    const int n0 = bn * BN + tx * TN;

    float bl[TN];
#pragma unroll
    for (int j = 0; j < TN; ++j) bl[j] = __ldg(bias + n0 + j);

#pragma unroll
    for (int i = 0; i < TM; ++i) {
        const float2 p0 = unpack_f32x2(acc[i][0]);
        const float2 p1 = unpack_f32x2(acc[i][1]);
        const float2 p2 = unpack_f32x2(acc[i][2]);
        const float2 p3 = unpack_f32x2(acc[i][3]);
        float4 o0, o1;
        o0.x = p0.x + bl[0]; o0.y = p0.y + bl[1];
        o0.z = p1.x + bl[2]; o0.w = p1.y + bl[3];
        o1.x = p2.x + bl[4]; o1.y = p2.y + bl[5];
        o1.z = p3.x + bl[6]; o1.w = p3.y + bl[7];
        float* dst = out + (size_t)(m0 + i) * ODIM + n0;
        *reinterpret_cast<float4*>(dst)     = o0;
        *reinterpret_cast<float4*>(dst + 4) = o1;
    }
}

// ---------------------------------------------------------------------------
// Launch: inputs per metadata order: X, A (unused), W, b, sampled_idx
// ---------------------------------------------------------------------------
extern "C" void kernel_launch(void* const* d_in, const int* in_sizes, int n_in,
                              void* d_out, int out_size)
{
    const float* X    = (const float*)d_in[0];
    // d_in[1] = A, dead input (values never influence output)
    const float* W    = (const float*)d_in[2];
    const float* bias = (const float*)d_in[3];
    const int*   idx  = (const int*)d_in[4];
    float*       out  = (float*)d_out;

    gather_mean_kernel<<<NNODES, 256>>>(X, idx);

    dim3 grid(ODIM / BN, NNODES / BM);   // (8, 64)
    gemm_concat_kernel<<<grid, 256>>>(X, W, bias, out);
}

// round 8
// speedup vs baseline: 3.0591x; 3.0591x over previous
#include <cuda_runtime.h>
#include <cstdint>

// Problem constants
#define NNODES 8192
#define FDIM   1024
#define ODIM   1024
#define KDIM   2048   // 2*FDIM
#define NNB    10

// GEMM tiling (Ampere-style mma.sync tf32, base sm_103 target — no tcgen05)
#define BM 128
#define BN 128
#define BK 32
#define NSTAGE 3
#define NKT (KDIM / BK)       // 64 k-tiles

// Padded smem strides (floats) for conflict-free fragment LDS
#define SA_STRIDE 36          // A tile row stride: bank = 4r+c, all distinct
#define SB_STRIDE 136         // B tile row stride: bank = 8kc+cg, all distinct
#define SA_FLOATS (BM * SA_STRIDE)            // 4608
#define SB_FLOATS (BK * SB_STRIDE)            // 4352
#define SMEM_FLOATS (NSTAGE * (SA_FLOATS + SB_FLOATS))
#define SMEM_BYTES  (SMEM_FLOATS * 4)         // 107520

// Scratch: A = [X | agg], tf32-rna-rounded, row-major [8192, 2048] (64 MB)
__device__ float g_Acat[(size_t)NNODES * KDIM];
// Scratch: W, tf32-rna-rounded, row-major [2048, 1024] (8 MB)
__device__ float g_W32[(size_t)KDIM * ODIM];

// ---------------------------------------------------------------------------
// PTX helpers (base-target instructions only: sm_80+ PTX)
// ---------------------------------------------------------------------------
__device__ __forceinline__ uint32_t smem_u32(const void* p) {
    uint32_t a;
    asm("{ .reg .u64 t; cvta.to.shared.u64 t, %1; cvt.u32.u64 %0, t; }"
        : "=r"(a) : "l"(p));
    return a;
}
__device__ __forceinline__ float rna_tf32(float x) {
    uint32_t r;
    asm("cvt.rna.tf32.f32 %0, %1;" : "=r"(r) : "f"(x));
    return __uint_as_float(r);
}
__device__ __forceinline__ void cp16(uint32_t dst, const float* src) {
    asm volatile("cp.async.cg.shared.global [%0], [%1], 16;"
                 :: "r"(dst), "l"(src) : "memory");
}
__device__ __forceinline__ void mma_tf32_16x8x8(float* d, const float* a,
                                                const float* b) {
    asm volatile(
        "mma.sync.aligned.m16n8k8.row.col.f32.tf32.tf32.f32 "
        "{%0,%1,%2,%3}, {%4,%5,%6,%7}, {%8,%9}, {%0,%1,%2,%3};"
        : "+f"(d[0]), "+f"(d[1]), "+f"(d[2]), "+f"(d[3])
        : "r"(__float_as_uint(a[0])), "r"(__float_as_uint(a[1])),
          "r"(__float_as_uint(a[2])), "r"(__float_as_uint(a[3])),
          "r"(__float_as_uint(b[0])), "r"(__float_as_uint(b[1])));
}

// ---------------------------------------------------------------------------
// Prep 1: rounded copy of X into A[:, 0:1024]
// ---------------------------------------------------------------------------
__global__ void __launch_bounds__(256) roundX_kernel(const float* __restrict__ X) {
    const int m = blockIdx.x;
    const int t = threadIdx.x;
    float4 v = __ldg(reinterpret_cast<const float4*>(X + (size_t)m * FDIM) + t);
    v.x = rna_tf32(v.x); v.y = rna_tf32(v.y);
    v.z = rna_tf32(v.z); v.w = rna_tf32(v.w);
    *(reinterpret_cast<float4*>(g_Acat + (size_t)m * KDIM) + t) = v;
}

// ---------------------------------------------------------------------------
// Prep 2: gather-mean into A[:, 1024:2048] (rounded)
// ---------------------------------------------------------------------------
__global__ void __launch_bounds__(256) gather_kernel(const float* __restrict__ X,
                                                     const int* __restrict__ idx) {
    const int m = blockIdx.x;
    const int t = threadIdx.x;
    const float4* Xv = reinterpret_cast<const float4*>(X);
    float4 acc = make_float4(0.f, 0.f, 0.f, 0.f);
#pragma unroll
    for (int j = 0; j < NNB; ++j) {
        const int nb = __ldg(idx + m * NNB + j);
        const float4 v = __ldg(Xv + (size_t)nb * (FDIM / 4) + t);
        acc.x += v.x; acc.y += v.y; acc.z += v.z; acc.w += v.w;
    }
    const float s = 1.0f / (float)NNB;
    acc.x = rna_tf32(acc.x * s); acc.y = rna_tf32(acc.y * s);
    acc.z = rna_tf32(acc.z * s); acc.w = rna_tf32(acc.w * s);
    *(reinterpret_cast<float4*>(g_Acat + (size_t)m * KDIM + FDIM) + t) = acc;
}

// ---------------------------------------------------------------------------
// Prep 3: elementwise rna-round of W (no transpose; consumed as [K, N])
// ---------------------------------------------------------------------------
__global__ void __launch_bounds__(256) roundW_kernel(const float* __restrict__ W) {
    const size_t i = ((size_t)blockIdx.x * 256 + threadIdx.x) * 4;
    float4 v = __ldg(reinterpret_cast<const float4*>(W + i));
    v.x = rna_tf32(v.x); v.y = rna_tf32(v.y);
    v.z = rna_tf32(v.z); v.w = rna_tf32(v.w);
    *reinterpret_cast<float4*>(g_W32 + i) = v;
}

// ---------------------------------------------------------------------------
// Main GEMM: out = A @ W + b   (M=8192, N=1024, K=2048)
// mma.sync m16n8k8 tf32, 8 warps (2M x 4N), warp tile 64x32, 3-stage cp.async.
// ---------------------------------------------------------------------------
__device__ __forceinline__ void load_stage(uint32_t sA, uint32_t sB,
                                           const float* __restrict__ gA,
                                           const float* __restrict__ gB,
                                           int kt, int tid) {
    const int k0 = kt * BK;
    // A tile: 128 rows x 32 floats = 1024 x 16B chunks, 4 per thread
#pragma unroll
    for (int i = 0; i < 4; ++i) {
        const int c = tid + i * 256;
        const int row = c >> 3, q = c & 7;
        cp16(sA + (uint32_t)(row * SA_STRIDE + q * 4) * 4,
             gA + (size_t)row * KDIM + k0 + q * 4);
    }
    // B tile: 32 rows x 128 floats = 1024 x 16B chunks, 4 per thread
#pragma unroll
    for (int i = 0; i < 4; ++i) {
        const int c = tid + i * 256;
        const int krow = c >> 5, q = c & 31;
        cp16(sB + (uint32_t)(krow * SB_STRIDE + q * 4) * 4,
             gB + (size_t)(k0 + krow) * ODIM + q * 4);
    }
}

__global__ void __launch_bounds__(256, 2) gemm_mma_kernel(
    const float* __restrict__ bias, float* __restrict__ out) {
    extern __shared__ float smem[];
    const uint32_t smem_b = smem_u32(smem);

    const int tid = threadIdx.x;
    const int wid = tid >> 5, lane = tid & 31;
    const int wm = wid & 1;          // warp M index (0..1) -> 64 rows
    const int wn = wid >> 1;         // warp N index (0..3) -> 32 cols
    const int m0 = blockIdx.y * BM;
    const int n0 = blockIdx.x * BN;

    const float* gA = g_Acat + (size_t)m0 * KDIM;
    const float* gB = g_W32 + n0;

    const int r  = lane >> 2;        // 0..7
    const int cl = lane & 3;         // 0..3

    float acc[4][4][4];
#pragma unroll
    for (int mt = 0; mt < 4; ++mt)
#pragma unroll
        for (int nt = 0; nt < 4; ++nt)
#pragma unroll
            for (int i = 0; i < 4; ++i) acc[mt][nt][i] = 0.f;

    // Prologue
    load_stage(smem_b, smem_b + NSTAGE * SA_FLOATS * 4, gA, gB, 0, tid);
    asm volatile("cp.async.commit_group;" ::: "memory");
    load_stage(smem_b + SA_FLOATS * 4,
               smem_b + (NSTAGE * SA_FLOATS + SB_FLOATS) * 4, gA, gB, 1, tid);
    asm volatile("cp.async.commit_group;" ::: "memory");

    for (int kt = 0; kt < NKT; ++kt) {
        asm volatile("cp.async.wait_group 1;" ::: "memory");
        __syncthreads();

        // Issue next stage's loads (buffer (kt+2)%3: reads finished at kt-1)
        const int ls = kt + 2;
        if (ls < NKT) {
            const int b = ls % NSTAGE;
            load_stage(smem_b + b * SA_FLOATS * 4,
                       smem_b + (NSTAGE * SA_FLOATS + b * SB_FLOATS) * 4,
                       gA, gB, ls, tid);
        }
        asm volatile("cp.async.commit_group;" ::: "memory");

        // Compute stage kt%3
        const int b = kt % NSTAGE;
        const float* As = smem + b * SA_FLOATS;
        const float* Bs = smem + NSTAGE * SA_FLOATS + b * SB_FLOATS;

#pragma unroll
        for (int ks = 0; ks < 4; ++ks) {
            const int k0s = ks * 8;

            float af[4][4];
#pragma unroll
            for (int mt = 0; mt < 4; ++mt) {
                const int row = wm * 64 + mt * 16 + r;
                const float* ap = As + row * SA_STRIDE + k0s + cl;
                af[mt][0] = ap[0];
                af[mt][1] = ap[8 * SA_STRIDE];
                af[mt][2] = ap[4];
                af[mt][3] = ap[8 * SA_STRIDE + 4];
            }
            float bf[4][2];
#pragma unroll
            for (int nt = 0; nt < 4; ++nt) {
                const int col = wn * 32 + nt * 8 + r;
                const float* bp = Bs + (k0s + cl) * SB_STRIDE + col;
                bf[nt][0] = bp[0];
                bf[nt][1] = bp[4 * SB_STRIDE];
            }
#pragma unroll
            for (int mt = 0; mt < 4; ++mt)
#pragma unroll
                for (int nt = 0; nt < 4; ++nt)
                    mma_tf32_16x8x8(acc[mt][nt], af[mt], bf[nt]);
        }
    }

    // Epilogue: c0,c1 -> (row, 2cl..2cl+1), c2,c3 -> (row+8, same cols)
#pragma unroll
    for (int nt = 0; nt < 4; ++nt) {
        const int col = n0 + wn * 32 + nt * 8 + cl * 2;
        const float2 bv = __ldg(reinterpret_cast<const float2*>(bias + col));
#pragma unroll
        for (int mt = 0; mt < 4; ++mt) {
            const int row = m0 + wm * 64 + mt * 16 + r;
            float2 o0, o1;
            o0.x = acc[mt][nt][0] + bv.x;
            o0.y = acc[mt][nt][1] + bv.y;
            o1.x = acc[mt][nt][2] + bv.x;
            o1.y = acc[mt][nt][3] + bv.y;
            *reinterpret_cast<float2*>(out + (size_t)row * ODIM + col) = o0;
            *reinterpret_cast<float2*>(out + (size_t)(row + 8) * ODIM + col) = o1;
        }
    }
}

// ---------------------------------------------------------------------------
// Launch: inputs per metadata order: X, A (dead), W, b, sampled_idx
// ---------------------------------------------------------------------------
extern "C" void kernel_launch(void* const* d_in, const int* in_sizes, int n_in,
                              void* d_out, int out_size) {
    const float* X    = (const float*)d_in[0];
    // d_in[1] = dense adjacency A, dead input (never influences output)
    const float* W    = (const float*)d_in[2];
    const float* bias = (const float*)d_in[3];
    const int*   idx  = (const int*)d_in[4];
    float*       out  = (float*)d_out;

    cudaFuncSetAttribute(gemm_mma_kernel,
                         cudaFuncAttributeMaxDynamicSharedMemorySize, SMEM_BYTES);

    roundX_kernel<<<NNODES, 256>>>(X);
    gather_kernel<<<NNODES, 256>>>(X, idx);
    roundW_kernel<<<(KDIM * ODIM) / (256 * 4), 256>>>(W);

    dim3 grid(ODIM / BN, NNODES / BM);   // (8, 64) = 512 CTAs
    gemm_mma_kernel<<<grid, 256, SMEM_BYTES>>>(bias, out);
}

// round 9
// speedup vs baseline: 3.2771x; 1.0713x over previous
#include <cuda_runtime.h>
#include <cstdint>

// Problem constants
#define NNODES 8192
#define FDIM   1024
#define ODIM   1024
#define KDIM   2048   // 2*FDIM
#define NNB    10

// GEMM tiling: CTA 128x256, 8 warps (2M x 4N), warp tile 64x64, BK=32, 3-stage
#define BM 128
#define BN 256
#define BK 32
#define NSTAGE 3
#define NKT (KDIM / BK)       // 64 k-tiles

// Padded smem strides (floats) for conflict-free fragment LDS
#define SA_STRIDE 36          // bank = (36r + cl) % 32 = 4r + cl, distinct
#define SB_STRIDE 264         // bank = (264cl + r) % 32 = 8cl + r, distinct
#define SA_BYTES (BM * SA_STRIDE * 4)   // 18432
#define SB_BYTES (BK * SB_STRIDE * 4)   // 33792
#define OFF_B (NSTAGE * SA_BYTES)       // 55296
#define SMEM_BYTES (NSTAGE * (SA_BYTES + SB_BYTES))   // 156672

// Scratch: A = [X | agg], tf32-rna-rounded, row-major [8192, 2048] (64 MB)
__device__ float g_Acat[(size_t)NNODES * KDIM];
// Scratch: W, tf32-rna-rounded, row-major [2048, 1024] (8 MB)
__device__ float g_W32[(size_t)KDIM * ODIM];

// ---------------------------------------------------------------------------
// PTX helpers (base-target sm_80+ PTX only — no tcgen05 on this toolchain)
// ---------------------------------------------------------------------------
__device__ __forceinline__ uint32_t smem_u32(const void* p) {
    uint32_t a;
    asm("{ .reg .u64 t; cvta.to.shared.u64 t, %1; cvt.u32.u64 %0, t; }"
        : "=r"(a) : "l"(p));
    return a;
}
__device__ __forceinline__ float rna_tf32(float x) {
    uint32_t r;
    asm("cvt.rna.tf32.f32 %0, %1;" : "=r"(r) : "f"(x));
    return __uint_as_float(r);
}
__device__ __forceinline__ void cp16(uint32_t dst, const float* src) {
    asm volatile("cp.async.cg.shared.global [%0], [%1], 16;"
                 :: "r"(dst), "l"(src) : "memory");
}
__device__ __forceinline__ void mma_tf32_16x8x8(float* d, const float* a,
                                                const float* b) {
    asm volatile(
        "mma.sync.aligned.m16n8k8.row.col.f32.tf32.tf32.f32 "
        "{%0,%1,%2,%3}, {%4,%5,%6,%7}, {%8,%9}, {%0,%1,%2,%3};"
        : "+f"(d[0]), "+f"(d[1]), "+f"(d[2]), "+f"(d[3])
        : "r"(__float_as_uint(a[0])), "r"(__float_as_uint(a[1])),
          "r"(__float_as_uint(a[2])), "r"(__float_as_uint(a[3])),
          "r"(__float_as_uint(b[0])), "r"(__float_as_uint(b[1])));
}

// ---------------------------------------------------------------------------
// Prep 1 (fused): rounded X copy into A[:, 0:1024] AND gather-mean into
// A[:, 1024:2048]. One block per row.
// ---------------------------------------------------------------------------
__global__ void __launch_bounds__(256) prepA_kernel(const float* __restrict__ X,
                                                    const int* __restrict__ idx) {
    const int m = blockIdx.x;
    const int t = threadIdx.x;
    const float4* Xv = reinterpret_cast<const float4*>(X);

    // own-row rounded copy
    float4 v = __ldg(Xv + (size_t)m * (FDIM / 4) + t);
    v.x = rna_tf32(v.x); v.y = rna_tf32(v.y);
    v.z = rna_tf32(v.z); v.w = rna_tf32(v.w);
    *(reinterpret_cast<float4*>(g_Acat + (size_t)m * KDIM) + t) = v;

    // neighbor mean
    float4 acc = make_float4(0.f, 0.f, 0.f, 0.f);
#pragma unroll
    for (int j = 0; j < NNB; ++j) {
        const int nb = __ldg(idx + m * NNB + j);
        const float4 w = __ldg(Xv + (size_t)nb * (FDIM / 4) + t);
        acc.x += w.x; acc.y += w.y; acc.z += w.z; acc.w += w.w;
    }
    const float s = 1.0f / (float)NNB;
    acc.x = rna_tf32(acc.x * s); acc.y = rna_tf32(acc.y * s);
    acc.z = rna_tf32(acc.z * s); acc.w = rna_tf32(acc.w * s);
    *(reinterpret_cast<float4*>(g_Acat + (size_t)m * KDIM + FDIM) + t) = acc;
}

// ---------------------------------------------------------------------------
// Prep 2: elementwise rna-round of W (consumed as [K, N])
// ---------------------------------------------------------------------------
__global__ void __launch_bounds__(256) roundW_kernel(const float* __restrict__ W) {
    const size_t i = ((size_t)blockIdx.x * 256 + threadIdx.x) * 4;
    float4 v = __ldg(reinterpret_cast<const float4*>(W + i));
    v.x = rna_tf32(v.x); v.y = rna_tf32(v.y);
    v.z = rna_tf32(v.z); v.w = rna_tf32(v.w);
    *reinterpret_cast<float4*>(g_W32 + i) = v;
}

// ---------------------------------------------------------------------------
// Main GEMM: out = A @ W + b   (M=8192, N=1024, K=2048)
// ---------------------------------------------------------------------------
__device__ __forceinline__ void load_stage(uint32_t sA, uint32_t sB,
                                           const float* __restrict__ gA,
                                           const float* __restrict__ gB,
                                           int kt, int tid) {
    const int k0 = kt * BK;
    // A tile: 128 rows x 32 floats = 1024 x 16B chunks, 4 per thread
#pragma unroll
    for (int i = 0; i < 4; ++i) {
        const int c = tid + i * 256;
        const int row = c >> 3, q = c & 7;
        cp16(sA + (uint32_t)(row * SA_STRIDE + q * 4) * 4,
             gA + (size_t)row * KDIM + k0 + q * 4);
    }
    // B tile: 32 k-rows x 256 floats = 2048 x 16B chunks, 8 per thread
#pragma unroll
    for (int i = 0; i < 8; ++i) {
        const int c = tid + i * 256;
        const int krow = c >> 6, q = c & 63;
        cp16(sB + (uint32_t)(krow * SB_STRIDE + q * 4) * 4,
             gB + (size_t)(k0 + krow) * ODIM + q * 4);
    }
}

__global__ void __launch_bounds__(256, 1) gemm_mma_kernel(
    const float* __restrict__ bias, float* __restrict__ out) {
    extern __shared__ float smem[];
    const uint32_t smem_b = smem_u32(smem);

    const int tid = threadIdx.x;
    const int wid = tid >> 5, lane = tid & 31;
    const int wm = wid & 1;          // warp M index (0..1) -> 64 rows
    const int wn = wid >> 1;         // warp N index (0..3) -> 64 cols
    const int m0 = blockIdx.y * BM;
    const int n0 = blockIdx.x * BN;

    const float* gA = g_Acat + (size_t)m0 * KDIM;
    const float* gB = g_W32 + n0;

    const int r  = lane >> 2;        // 0..7
    const int cl = lane & 3;         // 0..3

    float acc[4][8][4];
#pragma unroll
    for (int mt = 0; mt < 4; ++mt)
#pragma unroll
        for (int nt = 0; nt < 8; ++nt)
#pragma unroll
            for (int i = 0; i < 4; ++i) acc[mt][nt][i] = 0.f;

    // Prologue: stages 0, 1
    load_stage(smem_b, smem_b + OFF_B, gA, gB, 0, tid);
    asm volatile("cp.async.commit_group;" ::: "memory");
    load_stage(smem_b + SA_BYTES, smem_b + OFF_B + SB_BYTES, gA, gB, 1, tid);
    asm volatile("cp.async.commit_group;" ::: "memory");

    // Per-thread fragment base offsets (floats)
    const int aoff = (wm * 64 + r) * SA_STRIDE + cl;
    const int boff = cl * SB_STRIDE + wn * 64 + r;

    for (int kt = 0; kt < NKT; ++kt) {
        asm volatile("cp.async.wait_group 1;" ::: "memory");
        __syncthreads();

        // Issue next stage's loads (buffer (kt+2)%3, reads done at kt-1)
        const int ls = kt + 2;
        if (ls < NKT) {
            const int b = ls % NSTAGE;
            load_stage(smem_b + b * SA_BYTES, smem_b + OFF_B + b * SB_BYTES,
                       gA, gB, ls, tid);
        }
        asm volatile("cp.async.commit_group;" ::: "memory");

        const int b = kt % NSTAGE;
        const float* As = smem + (b * SA_BYTES) / 4;
        const float* Bs = smem + (OFF_B + b * SB_BYTES) / 4;

        float af[2][4][4], bf[2][8][2];

        // Load fragments for ks = 0 into buffer 0
#pragma unroll
        for (int mt = 0; mt < 4; ++mt) {
            const float* ap = As + aoff + mt * 16 * SA_STRIDE;
            af[0][mt][0] = ap[0];
            af[0][mt][1] = ap[8 * SA_STRIDE];
            af[0][mt][2] = ap[4];
            af[0][mt][3] = ap[8 * SA_STRIDE + 4];
        }
#pragma unroll
        for (int nt = 0; nt < 8; ++nt) {
            const float* bp = Bs + boff + nt * 8;
            bf[0][nt][0] = bp[0];
            bf[0][nt][1] = bp[4 * SB_STRIDE];
        }

#pragma unroll
        for (int ks = 0; ks < 4; ++ks) {
            const int cur = ks & 1, nxt = cur ^ 1;
            if (ks < 3) {
                const int k0s = (ks + 1) * 8;
#pragma unroll
                for (int mt = 0; mt < 4; ++mt) {
                    const float* ap = As + aoff + mt * 16 * SA_STRIDE + k0s;
                    af[nxt][mt][0] = ap[0];
                    af[nxt][mt][1] = ap[8 * SA_STRIDE];
                    af[nxt][mt][2] = ap[4];
                    af[nxt][mt][3] = ap[8 * SA_STRIDE + 4];
                }
#pragma unroll
                for (int nt = 0; nt < 8; ++nt) {
                    const float* bp = Bs + boff + k0s * SB_STRIDE + nt * 8;
                    bf[nxt][nt][0] = bp[0];
                    bf[nxt][nt][1] = bp[4 * SB_STRIDE];
                }
            }
#pragma unroll
            for (int mt = 0; mt < 4; ++mt)
#pragma unroll
                for (int nt = 0; nt < 8; ++nt)
                    mma_tf32_16x8x8(acc[mt][nt], af[cur][mt], bf[cur][nt]);
        }
    }

    // Epilogue
#pragma unroll
    for (int nt = 0; nt < 8; ++nt) {
        const int col = n0 + wn * 64 + nt * 8 + cl * 2;
        const float2 bv = __ldg(reinterpret_cast<const float2*>(bias + col));
#pragma unroll
        for (int mt = 0; mt < 4; ++mt) {
            const int row = m0 + wm * 64 + mt * 16 + r;
            float2 o0, o1;
            o0.x = acc[mt][nt][0] + bv.x;
            o0.y = acc[mt][nt][1] + bv.y;
            o1.x = acc[mt][nt][2] + bv.x;
            o1.y = acc[mt][nt][3] + bv.y;
            *reinterpret_cast<float2*>(out + (size_t)row * ODIM + col) = o0;
            *reinterpret_cast<float2*>(out + (size_t)(row + 8) * ODIM + col) = o1;
        }
    }
}

// ---------------------------------------------------------------------------
// Launch: inputs per metadata order: X, A (dead), W, b, sampled_idx
// ---------------------------------------------------------------------------
extern "C" void kernel_launch(void* const* d_in, const int* in_sizes, int n_in,
                              void* d_out, int out_size) {
    const float* X    = (const float*)d_in[0];
    // d_in[1] = dense adjacency A, dead input (never influences output)
    const float* W    = (const float*)d_in[2];
    const float* bias = (const float*)d_in[3];
    const int*   idx  = (const int*)d_in[4];
    float*       out  = (float*)d_out;

    cudaFuncSetAttribute(gemm_mma_kernel,
                         cudaFuncAttributeMaxDynamicSharedMemorySize, SMEM_BYTES);

    prepA_kernel<<<NNODES, 256>>>(X, idx);
    roundW_kernel<<<(KDIM * ODIM) / (256 * 4), 256>>>(W);

    dim3 grid(ODIM / BN, NNODES / BM);   // (4, 64) = 256 CTAs
    gemm_mma_kernel<<<grid, 256, SMEM_BYTES>>>(bias, out);
}